// round 12
// baseline (speedup 1.0000x reference)
#include <cuda_runtime.h>

#define T_LEN   16777216
#define BLOCK   256
#define ITEMS   32
#define TILE    4096                   // output region per block (halo kernel)
#define HALO    4096
#define SPAN    8192                   // HALO + TILE
#define NT_A    (T_LEN / TILE)         // 4096 blocks (halo kernel)
#define NWARP   (BLOCK / 32)
#define FULLMASK 0xffffffffu

// ---- fallback (lookback) kernel state; only used when a^4096 != 0 ----
#define TILE_F   8192
#define NT_F     (T_LEN / TILE_F)      // 2048 = 1<<11
#define NTF_LOG2 11
__device__ unsigned g_ctr;
__device__ unsigned g_flag[NT_F];
__device__ float2   g_part[NT_F];
__device__ float2   g_incl[NT_F];

__device__ __forceinline__ unsigned ld_acquire(const unsigned* p) {
    unsigned v;
    asm volatile("ld.acquire.gpu.global.b32 %0, [%1];" : "=r"(v) : "l"(p) : "memory");
    return v;
}
__device__ __forceinline__ void st_release(unsigned* p, unsigned v) {
    asm volatile("st.release.gpu.global.b32 [%0], %1;" :: "l"(p), "r"(v) : "memory");
}
__device__ __forceinline__ float pow_sq(float a, int sq) {  // a^(2^sq)
    #pragma unroll 1
    for (int k = 0; k < sq; k++) a *= a;
    return a;
}

// ============================================================================
// Kernel A: independent halo tiles. Active iff a^4096 == 0.0f (alpha >~ 0.021).
// Each block loads SPAN=8192 elems ending at its tile end, scans from zero at
// the halo start; the zero-init error is multiplied by a^4096 = 0 -> exact.
// Tile 0: generic scan + closed-form pin correction  s_t += a^(t+1) * y[0].
// ============================================================================
__global__ __launch_bounds__(BLOCK) void ses_halo(
    const float* __restrict__ y, const float* __restrict__ alpha_p,
    float* __restrict__ out)
{
    const float alpha = __ldg(alpha_p);
    const float a = 1.0f - alpha;
    if (pow_sq(a, 12) != 0.0f) return;           // a^4096: not our regime

    // Padded transpose buffer: float4 slot = Q + (Q>>3), conflict-free for
    // striped (consecutive Q) and blocked (Q = 8*tid + i) access.
    __shared__ float sbuf[SPAN + SPAN / 8];      // 36.9 KB
    __shared__ float sh_wB[NWARP];

    const int tid  = threadIdx.x;
    const int lane = tid & 31;
    const int wid  = tid >> 5;
    const int tile = blockIdx.x;

    float4* s4 = reinterpret_cast<float4*>(sbuf);

    // ---- striped coalesced load of [tileEndQ-2048, tileEndQ) quads ----
    {
        const float4* y4 = reinterpret_cast<const float4*>(y);
        const int baseQ = tile * (TILE / 4) - (HALO / 4); // may be -1024 (tile 0)
        #pragma unroll
        for (int j = 0; j < 8; j++) {
            const int Q = j * BLOCK + tid;
            const int gq = baseQ + Q;
            float4 val = (gq >= 0) ? y4[gq] : make_float4(0.f, 0.f, 0.f, 0.f);
            s4[Q + (Q >> 3)] = val;
        }
    }
    __syncthreads();

    // ---- blocked read + thread-local serial scan (zero carry-in) ----
    float v[ITEMS];
    #pragma unroll
    for (int i = 0; i < 8; i++) {
        const int Q = 8 * tid + i;
        float4 q = s4[Q + (Q >> 3)];
        v[4*i+0] = q.x; v[4*i+1] = q.y; v[4*i+2] = q.z; v[4*i+3] = q.w;
    }
    float B;
    {
        float p = 0.f;
        #pragma unroll
        for (int i = 0; i < ITEMS; i++) {
            p = fmaf(a, p, alpha * v[i]);
            v[i] = p;
        }
        B = p;
    }

    float a2 = a*a, a4 = a2*a2, a8 = a4*a4, a16 = a8*a8;
    const float a32 = a16 * a16;

    // ---- warp inclusive scan of B; window-A closed form a^(32d) ----
    float m = a32;
    #pragma unroll
    for (int d = 1; d < 32; d <<= 1) {
        float pB = __shfl_up_sync(FULLMASK, B, d);
        if (lane >= d) B = fmaf(m, pB, B);
        m = m * m;
    }
    const float A1024 = m;
    float exB = __shfl_up_sync(FULLMASK, B, 1);
    if (lane == 0) exB = 0.f;
    if (lane == 31) sh_wB[wid] = B;
    __syncthreads();

    float WB = 0.f;                               // prefix of warps 0..wid-1
    #pragma unroll
    for (int w = 0; w < NWARP; w++) if (w < wid) WB = fmaf(A1024, WB, sh_wB[w]);

    float exA = 1.f;                              // a^(32*lane)
    { float bp = a32; int e = lane;
      #pragma unroll
      for (int k = 0; k < 5; k++) { if (e & 1) exA *= bp; bp *= bp; e >>= 1; } }
    const float c = fmaf(exA, WB, exB);           // level just before this thread
                                                  // (span carry-in is exactly 0)
    // ---- fixup ----
    {
        float cp = c * a;
        #pragma unroll
        for (int i = 0; i < ITEMS; i++) { v[i] += cp; cp *= a; }
    }

    // ---- tile-0 pin correction: s_t += a^(t+1) * y0 ----
    if (tile == 0 && tid >= BLOCK / 2) {          // threads holding global idx >= 0
        const float y0 = __ldg(y);
        // first global idx of this thread: g0 = 32*tid - HALO = 32*(tid-128)
        float pw = a;                             // a^(g0+1) = a^(32*(tid-128)) * a
        { float bp = a32; int e = tid - BLOCK / 2;
          #pragma unroll
          for (int k = 0; k < 7; k++) { if (e & 1) pw *= bp; bp *= bp; e >>= 1; } }
        #pragma unroll
        for (int i = 0; i < ITEMS; i++) { v[i] = fmaf(pw, y0, v[i]); pw *= a; }
    }

    // ---- blocked -> SMEM (own slots only: race-free), striped stores ----
    #pragma unroll
    for (int i = 0; i < 8; i++) {
        const int Q = 8 * tid + i;
        s4[Q + (Q >> 3)] = make_float4(v[4*i+0], v[4*i+1], v[4*i+2], v[4*i+3]);
    }
    __syncthreads();

    {
        // output quads: local Q in [1024, 2048) -> global quad tile*1024 + Q - 1024
        float4* o4 = reinterpret_cast<float4*>(out) + (size_t)tile * (TILE / 4) - (HALO / 4);
        if (tile != NT_A - 1) {
            #pragma unroll
            for (int j = 0; j < 4; j++) {
                const int Q = (HALO / 4) + j * BLOCK + tid;
                __stcs(&o4[Q], s4[Q + (Q >> 3)]);
            }
        } else {
            // last tile: output length T_LEN-1, never write index T_LEN-1
            const long long obase = (long long)tile * TILE - HALO;
            #pragma unroll
            for (int j = 0; j < 4; j++) {
                const int Q = (HALO / 4) + j * BLOCK + tid;
                float4 q = s4[Q + (Q >> 3)];
                const long long g = obase + 4LL * Q;
                if (g + 4 <= (long long)(T_LEN - 1)) {
                    __stcs(&o4[Q], q);
                } else {
                    float* op = out + g;
                    if (g + 0 < (long long)(T_LEN - 1)) op[0] = q.x;
                    if (g + 1 < (long long)(T_LEN - 1)) op[1] = q.y;
                    if (g + 2 < (long long)(T_LEN - 1)) op[2] = q.z;
                    if (g + 3 < (long long)(T_LEN - 1)) op[3] = q.w;
                }
            }
        }
    }
}

// ============================================================================
// Kernel B: proven decoupled-lookback path (R11). Active iff a^4096 != 0.
// ============================================================================
__global__ __launch_bounds__(BLOCK) void ses_scan_fb(
    const float* __restrict__ y, const float* __restrict__ alpha_p,
    float* __restrict__ out)
{
    const float alpha = __ldg(alpha_p);
    const float a = 1.0f - alpha;
    if (pow_sq(a, 12) == 0.0f) return;           // halo kernel handled it

    __shared__ float sbuf[TILE_F + TILE_F / 8];
    __shared__ float sh_wB[NWARP];
    __shared__ float sh_carry;
    __shared__ unsigned sh_ticket;

    const int tid  = threadIdx.x;
    const int lane = tid & 31;
    const int wid  = tid >> 5;

    if (tid == 0) sh_ticket = atomicAdd(&g_ctr, 1u);
    __syncthreads();
    const unsigned ticket = sh_ticket;
    const int tile = (int)(ticket & (NT_F - 1u));
    const unsigned fPart = 3u * (ticket >> NTF_LOG2) + 1u;
    const unsigned fIncl = fPart + 1u;

    float4* s4 = reinterpret_cast<float4*>(sbuf);
    {
        const float4* yin = reinterpret_cast<const float4*>(y) + (size_t)tile * (TILE_F / 4);
        #pragma unroll
        for (int j = 0; j < 8; j++) {
            const int Q = j * BLOCK + tid;
            s4[Q + (Q >> 3)] = yin[Q];
        }
    }
    __syncthreads();

    float v[ITEMS];
    #pragma unroll
    for (int i = 0; i < 8; i++) {
        const int Q = 8 * tid + i;
        float4 q = s4[Q + (Q >> 3)];
        v[4*i+0] = q.x; v[4*i+1] = q.y; v[4*i+2] = q.z; v[4*i+3] = q.w;
    }
    float B;
    {
        float p = 0.f;
        const bool first = (tile == 0 && tid == 0);
        #pragma unroll
        for (int i = 0; i < ITEMS; i++) {
            float aa = a, bb = alpha * v[i];
            if (first && i == 0) { aa = 0.f; bb = v[0]; }
            p = fmaf(aa, p, bb);
            v[i] = p;
        }
        B = p;
    }

    float a2 = a*a, a4 = a2*a2, a8 = a4*a4, a16 = a8*a8;
    const float a32 = a16 * a16;

    float m = a32;
    #pragma unroll
    for (int d = 1; d < 32; d <<= 1) {
        float pB = __shfl_up_sync(FULLMASK, B, d);
        if (lane >= d) B = fmaf(m, pB, B);
        m = m * m;
    }
    const float A1024 = m;
    float exB = __shfl_up_sync(FULLMASK, B, 1);
    if (lane == 0) exB = 0.f;
    if (lane == 31) sh_wB[wid] = B;
    __syncthreads();

    float WB = 0.f;
    #pragma unroll
    for (int w = 0; w < NWARP; w++) if (w < wid) WB = fmaf(A1024, WB, sh_wB[w]);

    float exA = 1.f;
    { float bp = a32; int e = lane;
      #pragma unroll
      for (int k = 0; k < 5; k++) { if (e & 1) exA *= bp; bp *= bp; e >>= 1; } }
    const float TexB = fmaf(exA, WB, exB);
    float TexA = exA;
    { float wp = A1024; int e = wid;
      #pragma unroll
      for (int k = 0; k < 3; k++) { if (e & 1) TexA *= wp; wp *= wp; e >>= 1; } }

    float aggA = 0.f, aggB = 0.f;
    if (tid == 0) {
        float gB = 0.f;
        #pragma unroll
        for (int w = 0; w < NWARP; w++) gB = fmaf(A1024, gB, sh_wB[w]);
        float A8192 = A1024 * A1024; A8192 *= A8192; A8192 *= A8192;
        aggA = (tile == 0) ? 0.f : A8192;
        aggB = gB;
        if (tile == 0) {
            __stcg(&g_incl[0], make_float2(0.f, gB));
            st_release(&g_flag[0], fIncl);
            sh_carry = 0.f;
        } else {
            __stcg(&g_part[tile], make_float2(A8192, gB));
            st_release(&g_flag[tile], fPart);
        }
    }

    if (wid == 0 && tile > 0) {
        __syncwarp();
        float accA = 1.f, accB = 0.f;
        int pred = tile - 1;
        for (;;) {
            const int idx = pred - lane;
            unsigned st = 2u;
            if (idx >= 0) {
                unsigned f = ld_acquire(&g_flag[idx]);
                while (f < fPart) { __nanosleep(32); f = ld_acquire(&g_flag[idx]); }
                st = f - fPart + 1u;
            }
            float mA, mB;
            if (idx < 0) { mA = 1.f; mB = 0.f; }
            else {
                float2 d2 = (st == 2u) ? __ldcg(&g_incl[idx]) : __ldcg(&g_part[idx]);
                mA = d2.x; mB = d2.y;
            }
            const unsigned bal = __ballot_sync(FULLMASK, st == 2u);
            const int mm = bal ? (__ffs(bal) - 1) : 32;
            const int start = (mm < 32) ? mm : 31;

            float cA = 1.f, cB = 0.f;
            for (int L = start; L >= 0; --L) {
                float sA = __shfl_sync(FULLMASK, mA, L);
                float sB = __shfl_sync(FULLMASK, mB, L);
                cB = fmaf(sA, cB, sB);
                cA = cA * sA;
            }
            float nB = fmaf(accA, cB, accB);
            accA = cA * accA;
            accB = nB;
            if (mm < 32 || accA == 0.0f) break;
            pred -= 32;
        }
        if (lane == 0) {
            __stcg(&g_incl[tile], make_float2(accA * aggA, fmaf(aggA, accB, aggB)));
            st_release(&g_flag[tile], fIncl);
            sh_carry = accB;
        }
    }
    __syncthreads();

    const float c = fmaf(TexA, sh_carry, TexB);
    {
        float cp = c * a;
        #pragma unroll
        for (int i = 0; i < ITEMS; i++) { v[i] += cp; cp *= a; }
    }

    #pragma unroll
    for (int i = 0; i < 8; i++) {
        const int Q = 8 * tid + i;
        s4[Q + (Q >> 3)] = make_float4(v[4*i+0], v[4*i+1], v[4*i+2], v[4*i+3]);
    }
    __syncthreads();

    {
        float4* o4 = reinterpret_cast<float4*>(out) + (size_t)tile * (TILE_F / 4);
        if (tile != NT_F - 1) {
            #pragma unroll
            for (int j = 0; j < 8; j++) {
                const int Q = j * BLOCK + tid;
                __stcs(&o4[Q], s4[Q + (Q >> 3)]);
            }
        } else {
            const long long tbase = (long long)tile * TILE_F;
            #pragma unroll
            for (int j = 0; j < 8; j++) {
                const int Q = j * BLOCK + tid;
                float4 q = s4[Q + (Q >> 3)];
                const long long g = tbase + 4LL * Q;
                if (g + 4 <= (long long)(T_LEN - 1)) {
                    __stcs(&o4[Q], q);
                } else {
                    float* op = out + g;
                    if (g + 0 < (long long)(T_LEN - 1)) op[0] = q.x;
                    if (g + 1 < (long long)(T_LEN - 1)) op[1] = q.y;
                    if (g + 2 < (long long)(T_LEN - 1)) op[2] = q.z;
                    if (g + 3 < (long long)(T_LEN - 1)) op[3] = q.w;
                }
            }
        }
    }
}

extern "C" void kernel_launch(void* const* d_in, const int* in_sizes, int n_in,
                              void* d_out, int out_size) {
    const float* y     = (const float*)d_in[0];   // timeseries, T_LEN fp32
    const float* alpha = (const float*)d_in[1];   // 1 fp32
    float* out = (float*)d_out;                   // T_LEN-1 fp32
    (void)in_sizes; (void)n_in; (void)out_size;

    ses_halo<<<NT_A, BLOCK>>>(y, alpha, out);     // active iff a^4096 == 0
    ses_scan_fb<<<NT_F, BLOCK>>>(y, alpha, out);  // active iff a^4096 != 0
}